// round 9
// baseline (speedup 1.0000x reference)
#include <cuda_runtime.h>
#include <math.h>

#define B_SZ 256
#define N_SZ 512
#define D_SZ 256
#define R_SZ 64
#define NT   16         // n-tiles per batch
#define TN   32         // rows per n-tile

// Scratch (allocation-free: __device__ globals)
__device__ float g_p[B_SZ * D_SZ];          // p = tok @ Wq^T @ Wk
__device__ float g_s[B_SZ * N_SZ];          // masked+scaled scores
__device__ float g_mt[B_SZ * NT];           // tile max
__device__ float g_zt[B_SZ * NT];           // tile sum of exp
__device__ float g_part[B_SZ * NT * D_SZ];  // unnormalized partial g
__device__ float g_g[B_SZ * D_SZ];          // final weighted sum

// ---------------------------------------------------------------------------
// k0: p[b,j] = sum_r (tok[b]·Wq[r]) * Wk[r,j]   fused, grid (8 j-tiles, 8 b-tiles)
// ---------------------------------------------------------------------------
__global__ void __launch_bounds__(256) k0_p(
    const float* __restrict__ tok,   // [256,256]
    const float* __restrict__ Wq,    // [64,256]
    const float* __restrict__ Wk)    // [64,256]
{
    __shared__ float tokS[32][260];  // pad: row stride 260 -> 4 distinct banks
    __shared__ float qS[32][64];
    const int j0 = blockIdx.x * 32;
    const int b0 = blockIdx.y * 32;
    const int tid = threadIdx.x;

    // load tok tile [32][256]
    #pragma unroll
    for (int i = 0; i < 32; i++) {
        const int idx = tid + 256 * i;            // 8192 elems
        tokS[idx >> 8][idx & 255] = tok[(b0 + (idx >> 8)) * D_SZ + (idx & 255)];
    }
    __syncthreads();

    // q tile: thread (row = tid>>3, rbase = (tid&7)*8) computes 8 q entries
    {
        const int row = tid >> 3;
        const int rbase = (tid & 7) * 8;
        float acc[8] = {0.f,0.f,0.f,0.f,0.f,0.f,0.f,0.f};
        for (int d = 0; d < D_SZ; d++) {
            const float tv = tokS[row][d];
            #pragma unroll
            for (int rr = 0; rr < 8; rr++)
                acc[rr] += tv * Wq[(rbase + rr) * D_SZ + d];
        }
        #pragma unroll
        for (int rr = 0; rr < 8; rr++)
            qS[row][rbase + rr] = acc[rr];
    }
    __syncthreads();

    // p tile: thread (col = tid&31, rows = (tid>>5)+8k)
    {
        const int col = tid & 31;
        const int r0 = tid >> 5;
        float acc[4] = {0.f, 0.f, 0.f, 0.f};
        for (int r = 0; r < R_SZ; r++) {
            const float wkv = Wk[r * D_SZ + j0 + col];
            #pragma unroll
            for (int k = 0; k < 4; k++)
                acc[k] += qS[r0 + 8 * k][r] * wkv;
        }
        #pragma unroll
        for (int k = 0; k < 4; k++)
            g_p[(b0 + r0 + 8 * k) * D_SZ + j0 + col] = acc[k];
    }
}

// ---------------------------------------------------------------------------
// K2a: ONE H read, tile lives in registers. TN=32 rows/CTA, grid (16,256).
// warp w owns rows {w, w+8, w+16, w+24}; lane l owns cols [4l,4l+4)+[128+4l,..).
// ---------------------------------------------------------------------------
__global__ void __launch_bounds__(256) k2a_pass(
    const float* __restrict__ H,
    const int* __restrict__ mask,
    const float* __restrict__ log_scale)
{
    __shared__ __align__(16) float p_s[D_SZ];
    __shared__ float s_s[TN];
    __shared__ float w_s[TN];
    __shared__ __align__(16) float4 part4[8 * 64];   // 8 KB: 8 warps x 256 cols

    const int b = blockIdx.y;
    const int t = blockIdx.x;
    const int n0 = t * TN;
    const int tid = threadIdx.x;
    const int w = tid >> 5, l = tid & 31;

    p_s[tid] = g_p[b * D_SZ + tid];
    const float inv_scale = 1.f / fmaxf(__expf(log_scale[0]), 0.1f);
    __syncthreads();

    const float* Hb = H + (size_t)b * N_SZ * D_SZ + (size_t)n0 * D_SZ;
    const float4* p4 = reinterpret_cast<const float4*>(p_s);
    const float4 pf0 = p4[l];
    const float4 pf1 = p4[l + 32];

    // Phase 1: front-batch 8 LDG.128 (4 rows x 2 fragments), keep in regs
    float4 f[4][2];
    #pragma unroll
    for (int r = 0; r < 4; r++) {
        const float4* h4 = reinterpret_cast<const float4*>(Hb + (w + 8 * r) * D_SZ);
        f[r][0] = h4[l];
        f[r][1] = h4[l + 32];
    }

    float sc[4];
    #pragma unroll
    for (int r = 0; r < 4; r++) {
        sc[r] = f[r][0].x * pf0.x + f[r][0].y * pf0.y
              + f[r][0].z * pf0.z + f[r][0].w * pf0.w
              + f[r][1].x * pf1.x + f[r][1].y * pf1.y
              + f[r][1].z * pf1.z + f[r][1].w * pf1.w;
    }
    #pragma unroll
    for (int off = 16; off > 0; off >>= 1) {
        #pragma unroll
        for (int r = 0; r < 4; r++)
            sc[r] += __shfl_xor_sync(0xffffffffu, sc[r], off);
    }
    if (l == 0) {
        #pragma unroll
        for (int r = 0; r < 4; r++) {
            const int n = w + 8 * r;
            const float s = (mask[b * N_SZ + n0 + n] != 0)
                            ? sc[r] * inv_scale : -INFINITY;
            s_s[n] = s;
            g_s[b * N_SZ + n0 + n] = s;
        }
    }
    __syncthreads();

    // Tile-local stats (warp 0, one score per lane)
    if (w == 0) {
        const float v = s_s[l];
        float vm = v;
        #pragma unroll
        for (int off = 16; off > 0; off >>= 1)
            vm = fmaxf(vm, __shfl_xor_sync(0xffffffffu, vm, off));
        const float mu = (vm == -INFINITY) ? 0.f : vm;     // NaN guard
        const float wv = __expf(v - mu);                   // exp(-inf)=0
        w_s[l] = wv;
        float z = wv;
        #pragma unroll
        for (int off = 16; off > 0; off >>= 1)
            z += __shfl_xor_sync(0xffffffffu, z, off);
        if (l == 0) {
            g_mt[b * NT + t] = vm;
            g_zt[b * NT + t] = z;
        }
    }
    __syncthreads();

    // Phase 2: pure register accumulation into lane-owned columns
    float4 acc0 = make_float4(0.f, 0.f, 0.f, 0.f);
    float4 acc1 = make_float4(0.f, 0.f, 0.f, 0.f);
    #pragma unroll
    for (int r = 0; r < 4; r++) {
        const float wn = w_s[w + 8 * r];
        acc0.x += wn * f[r][0].x;  acc0.y += wn * f[r][0].y;
        acc0.z += wn * f[r][0].z;  acc0.w += wn * f[r][0].w;
        acc1.x += wn * f[r][1].x;  acc1.y += wn * f[r][1].y;
        acc1.z += wn * f[r][1].z;  acc1.w += wn * f[r][1].w;
    }
    part4[w * 64 + l]      = acc0;    // cols [4l, 4l+4)
    part4[w * 64 + 32 + l] = acc1;    // cols [128+4l, ...)
    __syncthreads();

    // Phase 3: cross-warp sum, thread tid owns column tid
    const float* partf = reinterpret_cast<const float*>(part4);
    float acc = 0.f;
    #pragma unroll
    for (int ww = 0; ww < 8; ww++)
        acc += partf[ww * D_SZ + tid];
    g_part[(b * NT + t) * D_SZ + tid] = acc;
}

// ---------------------------------------------------------------------------
// K2b: combine tile stats -> exact alpha + final g.  grid 256 (b)
// ---------------------------------------------------------------------------
__global__ void __launch_bounds__(256) k2b_combine(
    float* __restrict__ alpha_out)
{
    __shared__ float f_s[NT];
    __shared__ float sm_M, sm_invZ;
    const int b = blockIdx.x;
    const int tid = threadIdx.x;

    if (tid < 32) {
        const float m_t = (tid < NT) ? g_mt[b * NT + tid] : -INFINITY;
        const float z_t = (tid < NT) ? g_zt[b * NT + tid] : 0.f;
        float M = m_t;
        #pragma unroll
        for (int off = 16; off > 0; off >>= 1)
            M = fmaxf(M, __shfl_xor_sync(0xffffffffu, M, off));
        const float e = (m_t == -INFINITY) ? 0.f : __expf(m_t - M);
        float Z = z_t * e;
        #pragma unroll
        for (int off = 16; off > 0; off >>= 1)
            Z += __shfl_xor_sync(0xffffffffu, Z, off);
        const float invZ = 1.f / Z;
        if (tid < NT) f_s[tid] = e * invZ;
        if (tid == 0) { sm_M = M; sm_invZ = invZ; }
    }
    __syncthreads();

    const float M = sm_M, invZ = sm_invZ;

    alpha_out[b * N_SZ + tid] = __expf(g_s[b * N_SZ + tid] - M) * invZ;
    alpha_out[b * N_SZ + tid + 256] =
        __expf(g_s[b * N_SZ + tid + 256] - M) * invZ;

    float acc = 0.f;
    #pragma unroll
    for (int t = 0; t < NT; t++)
        acc += f_s[t] * g_part[(b * NT + t) * D_SZ + tid];
    g_g[b * D_SZ + tid] = acc;
}

// ---------------------------------------------------------------------------
// K3: ctx[b,e] = sum_d g[b,d] * Wv[e,d]   (32x32 tiled NT GEMM)
// ---------------------------------------------------------------------------
__global__ void __launch_bounds__(256) k3_ctx(
    const float* __restrict__ Wv, float* __restrict__ ctx)
{
    __shared__ float Gs[32][33];
    __shared__ float Ws[32][33];
    const int e0 = blockIdx.x * 32, b0 = blockIdx.y * 32;
    const int tid = threadIdx.x, tx = tid & 31, ty = tid >> 5;
    float acc[4] = {0.f, 0.f, 0.f, 0.f};

    for (int d0 = 0; d0 < D_SZ; d0 += 32) {
        #pragma unroll
        for (int r = 0; r < 4; r++) {
            const int row = ty + 8 * r;
            Gs[row][tx] = g_g[(b0 + row) * D_SZ + d0 + tx];
            Ws[row][tx] = Wv[(e0 + row) * D_SZ + d0 + tx];
        }
        __syncthreads();
        #pragma unroll
        for (int kk = 0; kk < 32; kk++) {
            const float wv = Ws[tx][kk];
            #pragma unroll
            for (int r = 0; r < 4; r++)
                acc[r] += Gs[ty + 8 * r][kk] * wv;
        }
        __syncthreads();
    }
    #pragma unroll
    for (int r = 0; r < 4; r++)
        ctx[(b0 + ty + 8 * r) * D_SZ + e0 + tx] = acc[r];
}

// ---------------------------------------------------------------------------
extern "C" void kernel_launch(void* const* d_in, const int* in_sizes, int n_in,
                              void* d_out, int out_size) {
    const float* tok  = (const float*)d_in[0];
    const float* H    = (const float*)d_in[1];
    const int* mask   = (const int*)d_in[2];
    const float* Wq   = (const float*)d_in[3];
    const float* Wk   = (const float*)d_in[4];
    const float* Wv   = (const float*)d_in[5];
    const float* ls   = (const float*)d_in[6];

    float* out_alpha = (float*)d_out;                 // [256,512]
    float* out_ctx   = out_alpha + B_SZ * N_SZ;       // [256,256]

    k0_p<<<dim3(8, 8), 256>>>(tok, Wq, Wk);
    k2a_pass<<<dim3(NT, B_SZ), 256>>>(H, mask, ls);
    k2b_combine<<<B_SZ, 256>>>(out_alpha);
    k3_ctx<<<dim3(8, 8), 256>>>(Wv, out_ctx);
}

// round 10
// speedup vs baseline: 2.8894x; 2.8894x over previous
#include <cuda_runtime.h>
#include <math.h>

#define B_SZ 256
#define N_SZ 512
#define D_SZ 256
#define R_SZ 64
#define NT   8          // n-tiles per batch
#define TN   64         // rows per n-tile

// Scratch (allocation-free: __device__ globals)
__device__ float g_M[D_SZ * D_SZ];          // M = Wq^T @ Wk
__device__ float g_WvT[D_SZ * D_SZ];        // WvT[d][e] = Wv[e][d]
__device__ float g_p[B_SZ * D_SZ];          // p = tok @ M
__device__ float g_s[B_SZ * N_SZ];          // masked+scaled scores
__device__ float g_mt[B_SZ * NT];           // tile max
__device__ float g_zt[B_SZ * NT];           // tile sum of exp
__device__ float g_part[B_SZ * NT * D_SZ];  // unnormalized partial g

// ---------------------------------------------------------------------------
// prep: z=0 -> M tile (M = Wq^T @ Wk);  z=1 -> Wv transpose tile
// ---------------------------------------------------------------------------
__global__ void __launch_bounds__(256) k_prep(
    const float* __restrict__ Wq,    // [64, 256]
    const float* __restrict__ Wk,    // [64, 256]
    const float* __restrict__ Wv)    // [256, 256]
{
    const int tid = threadIdx.x, tx = tid & 31, ty = tid >> 5;

    if (blockIdx.z == 0) {
        __shared__ float A[32][33];
        __shared__ float Bs[32][33];
        const int d0 = blockIdx.y * 32, j0 = blockIdx.x * 32;
        float acc[4] = {0.f, 0.f, 0.f, 0.f};

        for (int k0 = 0; k0 < R_SZ; k0 += 32) {
            #pragma unroll
            for (int r = 0; r < 4; r++) {
                const int kk = ty + 8 * r;
                A[kk][tx]  = Wq[(k0 + kk) * D_SZ + d0 + tx];
                Bs[kk][tx] = Wk[(k0 + kk) * D_SZ + j0 + tx];
            }
            __syncthreads();
            #pragma unroll
            for (int kk = 0; kk < 32; kk++) {
                const float bv = Bs[kk][tx];
                #pragma unroll
                for (int r = 0; r < 4; r++)
                    acc[r] += A[kk][ty + 8 * r] * bv;
            }
            __syncthreads();
        }
        #pragma unroll
        for (int r = 0; r < 4; r++)
            g_M[(d0 + ty + 8 * r) * D_SZ + j0 + tx] = acc[r];
    } else {
        // Transpose Wv tile: WvT[d0+i][e0+j] = Wv[e0+j][d0+i]
        __shared__ float T[32][33];
        const int e0 = blockIdx.x * 32, d0 = blockIdx.y * 32;
        #pragma unroll
        for (int r = 0; r < 4; r++)
            T[ty + 8 * r][tx] = Wv[(e0 + ty + 8 * r) * D_SZ + d0 + tx];
        __syncthreads();
        #pragma unroll
        for (int r = 0; r < 4; r++)
            g_WvT[(d0 + ty + 8 * r) * D_SZ + e0 + tx] = T[tx][ty + 8 * r];
    }
}

// ---------------------------------------------------------------------------
// k1: p[b,j] = sum_d tok[b,d] * M[d,j]
// ---------------------------------------------------------------------------
__global__ void __launch_bounds__(256) k1_p(const float* __restrict__ tok)
{
    __shared__ float As[32][33];
    __shared__ float Bs[32][33];
    const int j0 = blockIdx.x * 32, b0 = blockIdx.y * 32;
    const int tid = threadIdx.x, tx = tid & 31, ty = tid >> 5;
    float acc[4] = {0.f, 0.f, 0.f, 0.f};

    for (int d0 = 0; d0 < D_SZ; d0 += 32) {
        #pragma unroll
        for (int r = 0; r < 4; r++) {
            const int row = ty + 8 * r;
            As[row][tx] = tok[(b0 + row) * D_SZ + d0 + tx];
            Bs[row][tx] = g_M[(d0 + row) * D_SZ + j0 + tx];
        }
        __syncthreads();
        #pragma unroll
        for (int kk = 0; kk < 32; kk++) {
            const float bv = Bs[kk][tx];
            #pragma unroll
            for (int r = 0; r < 4; r++)
                acc[r] += As[ty + 8 * r][kk] * bv;
        }
        __syncthreads();
    }
    #pragma unroll
    for (int r = 0; r < 4; r++)
        g_p[(b0 + ty + 8 * r) * D_SZ + j0 + tx] = acc[r];
}

// ---------------------------------------------------------------------------
// K2a (R7-proven): single logical H pass, phase-2 re-read hits L1/L2.
// ---------------------------------------------------------------------------
__global__ void __launch_bounds__(256) k2a_pass(
    const float* __restrict__ H,
    const int* __restrict__ mask,
    const float* __restrict__ log_scale)
{
    __shared__ __align__(16) float p_s[D_SZ];
    __shared__ float s_s[TN];
    __shared__ float w_s[TN];

    const int b = blockIdx.y;
    const int t = blockIdx.x;
    const int n0 = t * TN;
    const int tid = threadIdx.x;
    const int w = tid >> 5, l = tid & 31;

    p_s[tid] = g_p[b * D_SZ + tid];
    const float inv_scale = 1.f / fmaxf(__expf(log_scale[0]), 0.1f);
    __syncthreads();

    const float* Hb = H + (size_t)b * N_SZ * D_SZ + (size_t)n0 * D_SZ;
    const float4* p4 = reinterpret_cast<const float4*>(p_s);
    const float4 pf0 = p4[l];
    const float4 pf1 = p4[l + 32];

    // Phase 1: warp w computes rows n = w + 8*i, unrolled 2 for MLP
    #pragma unroll
    for (int i = 0; i < 8; i += 2) {
        const int na = w + 8 * i;
        const int nb = na + 8;
        const float4* h4a = reinterpret_cast<const float4*>(Hb + na * D_SZ);
        const float4* h4b = reinterpret_cast<const float4*>(Hb + nb * D_SZ);
        float4 a0 = h4a[l], a1 = h4a[l + 32];
        float4 b0 = h4b[l], b1 = h4b[l + 32];

        float pa = a0.x * pf0.x + a0.y * pf0.y + a0.z * pf0.z + a0.w * pf0.w
                 + a1.x * pf1.x + a1.y * pf1.y + a1.z * pf1.z + a1.w * pf1.w;
        float pb = b0.x * pf0.x + b0.y * pf0.y + b0.z * pf0.z + b0.w * pf0.w
                 + b1.x * pf1.x + b1.y * pf1.y + b1.z * pf1.z + b1.w * pf1.w;

        #pragma unroll
        for (int off = 16; off > 0; off >>= 1) {
            pa += __shfl_xor_sync(0xffffffffu, pa, off);
            pb += __shfl_xor_sync(0xffffffffu, pb, off);
        }
        if (l == 0) {
            float sa = (mask[b * N_SZ + n0 + na] != 0) ? pa * inv_scale : -INFINITY;
            float sb = (mask[b * N_SZ + n0 + nb] != 0) ? pb * inv_scale : -INFINITY;
            s_s[na] = sa;  g_s[b * N_SZ + n0 + na] = sa;
            s_s[nb] = sb;  g_s[b * N_SZ + n0 + nb] = sb;
        }
    }
    __syncthreads();

    // Tile-local softmax stats (warp 0)
    if (w == 0) {
        float v0 = s_s[l], v1 = s_s[l + 32];
        float v = fmaxf(v0, v1);
        #pragma unroll
        for (int off = 16; off > 0; off >>= 1)
            v = fmaxf(v, __shfl_xor_sync(0xffffffffu, v, off));
        const float m_t = v;
        const float mu = (m_t == -INFINITY) ? 0.f : m_t;   // NaN guard
        const float w0 = __expf(v0 - mu);
        const float w1 = __expf(v1 - mu);
        w_s[l] = w0;
        w_s[l + 32] = w1;
        float z = w0 + w1;
        #pragma unroll
        for (int off = 16; off > 0; off >>= 1)
            z += __shfl_xor_sync(0xffffffffu, z, off);
        if (l == 0) {
            g_mt[b * NT + t] = m_t;
            g_zt[b * NT + t] = z;
        }
    }
    __syncthreads();

    // Phase 2: partial g; re-read tile (cache hits), 4 independent accs
    float a0 = 0.f, a1 = 0.f, a2 = 0.f, a3 = 0.f;
    #pragma unroll 4
    for (int n = 0; n < TN; n += 4) {
        a0 += w_s[n]     * Hb[(n)     * D_SZ + tid];
        a1 += w_s[n + 1] * Hb[(n + 1) * D_SZ + tid];
        a2 += w_s[n + 2] * Hb[(n + 2) * D_SZ + tid];
        a3 += w_s[n + 3] * Hb[(n + 3) * D_SZ + tid];
    }
    g_part[(b * NT + t) * D_SZ + tid] = (a0 + a1) + (a2 + a3);
}

// ---------------------------------------------------------------------------
// K2b fused: combine stats -> alpha + g (smem) -> ctx[b,:] = g · WvT.
// grid 256 (b), block 256. WvT rows read coalesced; 256 KB -> L1/L2 resident.
// ---------------------------------------------------------------------------
__global__ void __launch_bounds__(256) k2b_fused(
    float* __restrict__ alpha_out,
    float* __restrict__ ctx)
{
    __shared__ float f_s[NT];
    __shared__ float sm_M, sm_invZ;
    __shared__ float gr[D_SZ];
    const int b = blockIdx.x;
    const int tid = threadIdx.x;

    if (tid < 32) {
        const float m_t = (tid < NT) ? g_mt[b * NT + tid] : -INFINITY;
        const float z_t = (tid < NT) ? g_zt[b * NT + tid] : 0.f;
        float M = m_t;
        #pragma unroll
        for (int off = 16; off > 0; off >>= 1)
            M = fmaxf(M, __shfl_xor_sync(0xffffffffu, M, off));
        const float e = (m_t == -INFINITY) ? 0.f : __expf(m_t - M);
        float Z = z_t * e;
        #pragma unroll
        for (int off = 16; off > 0; off >>= 1)
            Z += __shfl_xor_sync(0xffffffffu, Z, off);
        const float invZ = 1.f / Z;
        if (tid < NT) f_s[tid] = e * invZ;
        if (tid == 0) { sm_M = M; sm_invZ = invZ; }
    }
    __syncthreads();

    const float M = sm_M, invZ = sm_invZ;

    // exact alpha from stored scores (exp(-inf - M) = 0 for masked)
    alpha_out[b * N_SZ + tid] = __expf(g_s[b * N_SZ + tid] - M) * invZ;
    alpha_out[b * N_SZ + tid + 256] =
        __expf(g_s[b * N_SZ + tid + 256] - M) * invZ;

    // g[b,d] = sum_t f_t * g_part[b,t,d]  -> smem
    float acc = 0.f;
    #pragma unroll
    for (int t = 0; t < NT; t++)
        acc += f_s[t] * g_part[(b * NT + t) * D_SZ + tid];
    gr[tid] = acc;
    __syncthreads();

    // ctx[b,e] = sum_d gr[d] * WvT[d,e]   (coalesced over e = tid)
    float c0 = 0.f, c1 = 0.f, c2 = 0.f, c3 = 0.f;
    #pragma unroll 8
    for (int d = 0; d < D_SZ; d += 4) {
        c0 += gr[d]     * g_WvT[(d)     * D_SZ + tid];
        c1 += gr[d + 1] * g_WvT[(d + 1) * D_SZ + tid];
        c2 += gr[d + 2] * g_WvT[(d + 2) * D_SZ + tid];
        c3 += gr[d + 3] * g_WvT[(d + 3) * D_SZ + tid];
    }
    ctx[b * D_SZ + tid] = (c0 + c1) + (c2 + c3);
}

// ---------------------------------------------------------------------------
extern "C" void kernel_launch(void* const* d_in, const int* in_sizes, int n_in,
                              void* d_out, int out_size) {
    const float* tok  = (const float*)d_in[0];
    const float* H    = (const float*)d_in[1];
    const int* mask   = (const int*)d_in[2];
    const float* Wq   = (const float*)d_in[3];
    const float* Wk   = (const float*)d_in[4];
    const float* Wv   = (const float*)d_in[5];
    const float* ls   = (const float*)d_in[6];

    float* out_alpha = (float*)d_out;                 // [256,512]
    float* out_ctx   = out_alpha + B_SZ * N_SZ;       // [256,256]

    k_prep<<<dim3(8, 8, 2), 256>>>(Wq, Wk, Wv);
    k1_p<<<dim3(8, 8), 256>>>(tok);
    k2a_pass<<<dim3(NT, B_SZ), 256>>>(H, mask, ls);
    k2b_fused<<<B_SZ, 256>>>(out_alpha, out_ctx);
}

// round 11
// speedup vs baseline: 3.0117x; 1.0423x over previous
#include <cuda_runtime.h>
#include <math.h>

#define B_SZ 256
#define N_SZ 512
#define D_SZ 256
#define R_SZ 64
#define NT   8          // n-tiles per batch
#define TN   64         // rows per n-tile

// Scratch (allocation-free: __device__ globals)
__device__ float g_M[D_SZ * D_SZ];          // M = Wq^T @ Wk
__device__ float g_WvT[D_SZ * D_SZ];        // WvT[d][e] = Wv[e][d]
__device__ float g_p[B_SZ * D_SZ];          // p = tok @ M
__device__ float g_s[B_SZ * N_SZ];          // masked+scaled scores
__device__ float g_mt[B_SZ * NT];           // tile max
__device__ float g_zt[B_SZ * NT];           // tile sum of exp
__device__ float g_part[B_SZ * NT * D_SZ];  // unnormalized partial g

// ---------------------------------------------------------------------------
// prep: z=0 -> M tile (M = Wq^T @ Wk);  z=1 -> Wv transpose tile
// ---------------------------------------------------------------------------
__global__ void __launch_bounds__(256) k_prep(
    const float* __restrict__ Wq,    // [64, 256]
    const float* __restrict__ Wk,    // [64, 256]
    const float* __restrict__ Wv)    // [256, 256]
{
    const int tid = threadIdx.x, tx = tid & 31, ty = tid >> 5;

    if (blockIdx.z == 0) {
        __shared__ float A[32][33];
        __shared__ float Bs[32][33];
        const int d0 = blockIdx.y * 32, j0 = blockIdx.x * 32;
        float acc[4] = {0.f, 0.f, 0.f, 0.f};

        for (int k0 = 0; k0 < R_SZ; k0 += 32) {
            #pragma unroll
            for (int r = 0; r < 4; r++) {
                const int kk = ty + 8 * r;
                A[kk][tx]  = Wq[(k0 + kk) * D_SZ + d0 + tx];
                Bs[kk][tx] = Wk[(k0 + kk) * D_SZ + j0 + tx];
            }
            __syncthreads();
            #pragma unroll
            for (int kk = 0; kk < 32; kk++) {
                const float bv = Bs[kk][tx];
                #pragma unroll
                for (int r = 0; r < 4; r++)
                    acc[r] += A[kk][ty + 8 * r] * bv;
            }
            __syncthreads();
        }
        #pragma unroll
        for (int r = 0; r < 4; r++)
            g_M[(d0 + ty + 8 * r) * D_SZ + j0 + tx] = acc[r];
    } else {
        // Transpose Wv tile: WvT[d0+i][e0+j] = Wv[e0+j][d0+i]
        __shared__ float T[32][33];
        const int e0 = blockIdx.x * 32, d0 = blockIdx.y * 32;
        #pragma unroll
        for (int r = 0; r < 4; r++)
            T[ty + 8 * r][tx] = Wv[(e0 + ty + 8 * r) * D_SZ + d0 + tx];
        __syncthreads();
        #pragma unroll
        for (int r = 0; r < 4; r++)
            g_WvT[(d0 + ty + 8 * r) * D_SZ + e0 + tx] = T[tx][ty + 8 * r];
    }
}

// ---------------------------------------------------------------------------
// k1: p[b,j] = sum_d tok[b,d] * M[d,j]
// ---------------------------------------------------------------------------
__global__ void __launch_bounds__(256) k1_p(const float* __restrict__ tok)
{
    __shared__ float As[32][33];
    __shared__ float Bs[32][33];
    const int j0 = blockIdx.x * 32, b0 = blockIdx.y * 32;
    const int tid = threadIdx.x, tx = tid & 31, ty = tid >> 5;
    float acc[4] = {0.f, 0.f, 0.f, 0.f};

    for (int d0 = 0; d0 < D_SZ; d0 += 32) {
        #pragma unroll
        for (int r = 0; r < 4; r++) {
            const int row = ty + 8 * r;
            As[row][tx] = tok[(b0 + row) * D_SZ + d0 + tx];
            Bs[row][tx] = g_M[(d0 + row) * D_SZ + j0 + tx];
        }
        __syncthreads();
        #pragma unroll
        for (int kk = 0; kk < 32; kk++) {
            const float bv = Bs[kk][tx];
            #pragma unroll
            for (int r = 0; r < 4; r++)
                acc[r] += As[ty + 8 * r][kk] * bv;
        }
        __syncthreads();
    }
    #pragma unroll
    for (int r = 0; r < 4; r++)
        g_p[(b0 + ty + 8 * r) * D_SZ + j0 + tx] = acc[r];
}

// ---------------------------------------------------------------------------
// K2a (R7-proven): single logical H pass, phase-2 re-read hits L1/L2.
// ---------------------------------------------------------------------------
__global__ void __launch_bounds__(256) k2a_pass(
    const float* __restrict__ H,
    const int* __restrict__ mask,
    const float* __restrict__ log_scale)
{
    __shared__ __align__(16) float p_s[D_SZ];
    __shared__ float s_s[TN];
    __shared__ float w_s[TN];

    const int b = blockIdx.y;
    const int t = blockIdx.x;
    const int n0 = t * TN;
    const int tid = threadIdx.x;
    const int w = tid >> 5, l = tid & 31;

    p_s[tid] = g_p[b * D_SZ + tid];
    const float inv_scale = 1.f / fmaxf(__expf(log_scale[0]), 0.1f);
    __syncthreads();

    const float* Hb = H + (size_t)b * N_SZ * D_SZ + (size_t)n0 * D_SZ;
    const float4* p4 = reinterpret_cast<const float4*>(p_s);
    const float4 pf0 = p4[l];
    const float4 pf1 = p4[l + 32];

    // Phase 1: warp w computes rows n = w + 8*i, unrolled 2 for MLP
    #pragma unroll
    for (int i = 0; i < 8; i += 2) {
        const int na = w + 8 * i;
        const int nb = na + 8;
        const float4* h4a = reinterpret_cast<const float4*>(Hb + na * D_SZ);
        const float4* h4b = reinterpret_cast<const float4*>(Hb + nb * D_SZ);
        float4 a0 = h4a[l], a1 = h4a[l + 32];
        float4 b0 = h4b[l], b1 = h4b[l + 32];

        float pa = a0.x * pf0.x + a0.y * pf0.y + a0.z * pf0.z + a0.w * pf0.w
                 + a1.x * pf1.x + a1.y * pf1.y + a1.z * pf1.z + a1.w * pf1.w;
        float pb = b0.x * pf0.x + b0.y * pf0.y + b0.z * pf0.z + b0.w * pf0.w
                 + b1.x * pf1.x + b1.y * pf1.y + b1.z * pf1.z + b1.w * pf1.w;

        #pragma unroll
        for (int off = 16; off > 0; off >>= 1) {
            pa += __shfl_xor_sync(0xffffffffu, pa, off);
            pb += __shfl_xor_sync(0xffffffffu, pb, off);
        }
        if (l == 0) {
            float sa = (mask[b * N_SZ + n0 + na] != 0) ? pa * inv_scale : -INFINITY;
            float sb = (mask[b * N_SZ + n0 + nb] != 0) ? pb * inv_scale : -INFINITY;
            s_s[na] = sa;  g_s[b * N_SZ + n0 + na] = sa;
            s_s[nb] = sb;  g_s[b * N_SZ + n0 + nb] = sb;
        }
    }
    __syncthreads();

    // Tile-local softmax stats (warp 0)
    if (w == 0) {
        float v0 = s_s[l], v1 = s_s[l + 32];
        float v = fmaxf(v0, v1);
        #pragma unroll
        for (int off = 16; off > 0; off >>= 1)
            v = fmaxf(v, __shfl_xor_sync(0xffffffffu, v, off));
        const float m_t = v;
        const float mu = (m_t == -INFINITY) ? 0.f : m_t;   // NaN guard
        const float w0 = __expf(v0 - mu);
        const float w1 = __expf(v1 - mu);
        w_s[l] = w0;
        w_s[l + 32] = w1;
        float z = w0 + w1;
        #pragma unroll
        for (int off = 16; off > 0; off >>= 1)
            z += __shfl_xor_sync(0xffffffffu, z, off);
        if (l == 0) {
            g_mt[b * NT + t] = m_t;
            g_zt[b * NT + t] = z;
        }
    }
    __syncthreads();

    // Phase 2: partial g; re-read tile (cache hits), 4 independent accs
    float a0 = 0.f, a1 = 0.f, a2 = 0.f, a3 = 0.f;
    #pragma unroll 4
    for (int n = 0; n < TN; n += 4) {
        a0 += w_s[n]     * Hb[(n)     * D_SZ + tid];
        a1 += w_s[n + 1] * Hb[(n + 1) * D_SZ + tid];
        a2 += w_s[n + 2] * Hb[(n + 2) * D_SZ + tid];
        a3 += w_s[n + 3] * Hb[(n + 3) * D_SZ + tid];
    }
    g_part[(b * NT + t) * D_SZ + tid] = (a0 + a1) + (a2 + a3);
}

// ---------------------------------------------------------------------------
// K2b fused v2: grid (4 e-quarters, 256 b).  Each CTA: combine stats ->
// gr[256] (redundant x4, cheap) -> 64 e-columns of ctx via 64x4 thread layout.
// The x==0 CTA column also writes exact alpha.
// ---------------------------------------------------------------------------
__global__ void __launch_bounds__(256) k2b_fused(
    float* __restrict__ alpha_out,
    float* __restrict__ ctx)
{
    __shared__ float f_s[NT];
    __shared__ float sm_M, sm_invZ;
    __shared__ float gr[D_SZ];
    __shared__ float red[256];
    const int b = blockIdx.y;
    const int q = blockIdx.x;          // e-quarter
    const int e0 = q * 64;
    const int tid = threadIdx.x;

    if (tid < 32) {
        const float m_t = (tid < NT) ? g_mt[b * NT + tid] : -INFINITY;
        const float z_t = (tid < NT) ? g_zt[b * NT + tid] : 0.f;
        float M = m_t;
        #pragma unroll
        for (int off = 16; off > 0; off >>= 1)
            M = fmaxf(M, __shfl_xor_sync(0xffffffffu, M, off));
        const float e = (m_t == -INFINITY) ? 0.f : __expf(m_t - M);
        float Z = z_t * e;
        #pragma unroll
        for (int off = 16; off > 0; off >>= 1)
            Z += __shfl_xor_sync(0xffffffffu, Z, off);
        const float invZ = 1.f / Z;
        if (tid < NT) f_s[tid] = e * invZ;
        if (tid == 0) { sm_M = M; sm_invZ = invZ; }
    }
    __syncthreads();

    const float M = sm_M, invZ = sm_invZ;

    // exact alpha (only the q==0 CTA column writes it)
    if (q == 0) {
        alpha_out[b * N_SZ + tid] = __expf(g_s[b * N_SZ + tid] - M) * invZ;
        alpha_out[b * N_SZ + tid + 256] =
            __expf(g_s[b * N_SZ + tid + 256] - M) * invZ;
    }

    // g[b,d] = sum_t f_t * g_part[b,t,d]  -> smem (redundant per quarter)
    float acc = 0.f;
    #pragma unroll
    for (int t = 0; t < NT; t++)
        acc += f_s[t] * g_part[(b * NT + t) * D_SZ + tid];
    gr[tid] = acc;
    __syncthreads();

    // ctx[b, e0+c] partials: thread (c = tid&63, dg = tid>>6) sums 64 d's
    {
        const int c = tid & 63;
        const int dg = (tid >> 6) * 64;
        float c0 = 0.f, c1 = 0.f, c2 = 0.f, c3 = 0.f;
        #pragma unroll 4
        for (int dd = 0; dd < 64; dd += 4) {
            c0 += gr[dg + dd]     * g_WvT[(dg + dd)     * D_SZ + e0 + c];
            c1 += gr[dg + dd + 1] * g_WvT[(dg + dd + 1) * D_SZ + e0 + c];
            c2 += gr[dg + dd + 2] * g_WvT[(dg + dd + 2) * D_SZ + e0 + c];
            c3 += gr[dg + dd + 3] * g_WvT[(dg + dd + 3) * D_SZ + e0 + c];
        }
        red[tid] = (c0 + c1) + (c2 + c3);
    }
    __syncthreads();

    if (tid < 64)
        ctx[b * D_SZ + e0 + tid] =
            (red[tid] + red[tid + 64]) + (red[tid + 128] + red[tid + 192]);
}

// ---------------------------------------------------------------------------
extern "C" void kernel_launch(void* const* d_in, const int* in_sizes, int n_in,
                              void* d_out, int out_size) {
    const float* tok  = (const float*)d_in[0];
    const float* H    = (const float*)d_in[1];
    const int* mask   = (const int*)d_in[2];
    const float* Wq   = (const float*)d_in[3];
    const float* Wk   = (const float*)d_in[4];
    const float* Wv   = (const float*)d_in[5];
    const float* ls   = (const float*)d_in[6];

    float* out_alpha = (float*)d_out;                 // [256,512]
    float* out_ctx   = out_alpha + B_SZ * N_SZ;       // [256,256]

    k_prep<<<dim3(8, 8, 2), 256>>>(Wq, Wk, Wv);
    k1_p<<<dim3(8, 8), 256>>>(tok);
    k2a_pass<<<dim3(NT, B_SZ), 256>>>(H, mask, ls);
    k2b_fused<<<dim3(4, B_SZ), 256>>>(out_alpha, out_ctx);
}

// round 12
// speedup vs baseline: 3.2371x; 1.0749x over previous
#include <cuda_runtime.h>
#include <math.h>

#define B_SZ 256
#define N_SZ 512
#define D_SZ 256
#define R_SZ 64
#define NT   16         // n-tiles per batch
#define TN   32         // rows per n-tile

// Scratch (allocation-free: __device__ globals)
__device__ float g_M[D_SZ * D_SZ];          // M = Wq^T @ Wk
__device__ float g_WvT[D_SZ * D_SZ];        // WvT[d][e] = Wv[e][d]
__device__ float g_p[B_SZ * D_SZ];          // p = tok @ M
__device__ float g_s[B_SZ * N_SZ];          // masked+scaled scores
__device__ float g_mt[B_SZ * NT];           // tile max
__device__ float g_zt[B_SZ * NT];           // tile sum of exp
__device__ float g_part[B_SZ * NT * D_SZ];  // unnormalized partial g

// ---------------------------------------------------------------------------
// prep: z=0 -> M tile (M = Wq^T @ Wk);  z=1 -> Wv transpose tile
// ---------------------------------------------------------------------------
__global__ void __launch_bounds__(256) k_prep(
    const float* __restrict__ Wq,    // [64, 256]
    const float* __restrict__ Wk,    // [64, 256]
    const float* __restrict__ Wv)    // [256, 256]
{
    const int tid = threadIdx.x, tx = tid & 31, ty = tid >> 5;

    if (blockIdx.z == 0) {
        __shared__ float A[32][33];
        __shared__ float Bs[32][33];
        const int d0 = blockIdx.y * 32, j0 = blockIdx.x * 32;
        float acc[4] = {0.f, 0.f, 0.f, 0.f};

        for (int k0 = 0; k0 < R_SZ; k0 += 32) {
            #pragma unroll
            for (int r = 0; r < 4; r++) {
                const int kk = ty + 8 * r;
                A[kk][tx]  = Wq[(k0 + kk) * D_SZ + d0 + tx];
                Bs[kk][tx] = Wk[(k0 + kk) * D_SZ + j0 + tx];
            }
            __syncthreads();
            #pragma unroll
            for (int kk = 0; kk < 32; kk++) {
                const float bv = Bs[kk][tx];
                #pragma unroll
                for (int r = 0; r < 4; r++)
                    acc[r] += A[kk][ty + 8 * r] * bv;
            }
            __syncthreads();
        }
        #pragma unroll
        for (int r = 0; r < 4; r++)
            g_M[(d0 + ty + 8 * r) * D_SZ + j0 + tx] = acc[r];
    } else {
        __shared__ float T[32][33];
        const int e0 = blockIdx.x * 32, d0 = blockIdx.y * 32;
        #pragma unroll
        for (int r = 0; r < 4; r++)
            T[ty + 8 * r][tx] = Wv[(e0 + ty + 8 * r) * D_SZ + d0 + tx];
        __syncthreads();
        #pragma unroll
        for (int r = 0; r < 4; r++)
            g_WvT[(d0 + ty + 8 * r) * D_SZ + e0 + tx] = T[tx][ty + 8 * r];
    }
}

// ---------------------------------------------------------------------------
// k1: p[b,j] = sum_d tok[b,d] * M[d,j]
// ---------------------------------------------------------------------------
__global__ void __launch_bounds__(256) k1_p(const float* __restrict__ tok)
{
    __shared__ float As[32][33];
    __shared__ float Bs[32][33];
    const int j0 = blockIdx.x * 32, b0 = blockIdx.y * 32;
    const int tid = threadIdx.x, tx = tid & 31, ty = tid >> 5;
    float acc[4] = {0.f, 0.f, 0.f, 0.f};

    for (int d0 = 0; d0 < D_SZ; d0 += 32) {
        #pragma unroll
        for (int r = 0; r < 4; r++) {
            const int row = ty + 8 * r;
            As[row][tx] = tok[(b0 + row) * D_SZ + d0 + tx];
            Bs[row][tx] = g_M[(d0 + row) * D_SZ + j0 + tx];
        }
        __syncthreads();
        #pragma unroll
        for (int kk = 0; kk < 32; kk++) {
            const float bv = Bs[kk][tx];
            #pragma unroll
            for (int r = 0; r < 4; r++)
                acc[r] += As[ty + 8 * r][kk] * bv;
        }
        __syncthreads();
    }
    #pragma unroll
    for (int r = 0; r < 4; r++)
        g_p[(b0 + ty + 8 * r) * D_SZ + j0 + tx] = acc[r];
}

// ---------------------------------------------------------------------------
// K2a: ONE DRAM read of H; tile lives in registers (R8 version, grid 4096).
// warp w owns rows {w, w+8, w+16, w+24}; lane l owns cols [4l,4l+4)+[128+4l,..).
// ---------------------------------------------------------------------------
__global__ void __launch_bounds__(256) k2a_pass(
    const float* __restrict__ H,
    const int* __restrict__ mask,
    const float* __restrict__ log_scale)
{
    __shared__ __align__(16) float p_s[D_SZ];
    __shared__ float s_s[TN];
    __shared__ float w_s[TN];
    __shared__ __align__(16) float4 part4[8 * 64];   // 8 KB

    const int b = blockIdx.y;
    const int t = blockIdx.x;
    const int n0 = t * TN;
    const int tid = threadIdx.x;
    const int w = tid >> 5, l = tid & 31;

    p_s[tid] = g_p[b * D_SZ + tid];
    const float inv_scale = 1.f / fmaxf(__expf(log_scale[0]), 0.1f);
    __syncthreads();

    const float* Hb = H + (size_t)b * N_SZ * D_SZ + (size_t)n0 * D_SZ;
    const float4* p4 = reinterpret_cast<const float4*>(p_s);
    const float4 pf0 = p4[l];
    const float4 pf1 = p4[l + 32];

    // Phase 1: front-batch 8 LDG.128 (4 rows x 2 fragments), keep in regs
    float4 f[4][2];
    #pragma unroll
    for (int r = 0; r < 4; r++) {
        const float4* h4 = reinterpret_cast<const float4*>(Hb + (w + 8 * r) * D_SZ);
        f[r][0] = h4[l];
        f[r][1] = h4[l + 32];
    }

    float sc[4];
    #pragma unroll
    for (int r = 0; r < 4; r++) {
        sc[r] = f[r][0].x * pf0.x + f[r][0].y * pf0.y
              + f[r][0].z * pf0.z + f[r][0].w * pf0.w
              + f[r][1].x * pf1.x + f[r][1].y * pf1.y
              + f[r][1].z * pf1.z + f[r][1].w * pf1.w;
    }
    #pragma unroll
    for (int off = 16; off > 0; off >>= 1) {
        #pragma unroll
        for (int r = 0; r < 4; r++)
            sc[r] += __shfl_xor_sync(0xffffffffu, sc[r], off);
    }
    if (l == 0) {
        #pragma unroll
        for (int r = 0; r < 4; r++) {
            const int n = w + 8 * r;
            const float s = (mask[b * N_SZ + n0 + n] != 0)
                            ? sc[r] * inv_scale : -INFINITY;
            s_s[n] = s;
            g_s[b * N_SZ + n0 + n] = s;
        }
    }
    __syncthreads();

    // Tile-local stats (warp 0, one score per lane)
    if (w == 0) {
        const float v = s_s[l];
        float vm = v;
        #pragma unroll
        for (int off = 16; off > 0; off >>= 1)
            vm = fmaxf(vm, __shfl_xor_sync(0xffffffffu, vm, off));
        const float mu = (vm == -INFINITY) ? 0.f : vm;     // NaN guard
        const float wv = __expf(v - mu);                   // exp(-inf)=0
        w_s[l] = wv;
        float z = wv;
        #pragma unroll
        for (int off = 16; off > 0; off >>= 1)
            z += __shfl_xor_sync(0xffffffffu, z, off);
        if (l == 0) {
            g_mt[b * NT + t] = vm;
            g_zt[b * NT + t] = z;
        }
    }
    __syncthreads();

    // Phase 2: pure register accumulation into lane-owned columns
    float4 acc0 = make_float4(0.f, 0.f, 0.f, 0.f);
    float4 acc1 = make_float4(0.f, 0.f, 0.f, 0.f);
    #pragma unroll
    for (int r = 0; r < 4; r++) {
        const float wn = w_s[w + 8 * r];
        acc0.x += wn * f[r][0].x;  acc0.y += wn * f[r][0].y;
        acc0.z += wn * f[r][0].z;  acc0.w += wn * f[r][0].w;
        acc1.x += wn * f[r][1].x;  acc1.y += wn * f[r][1].y;
        acc1.z += wn * f[r][1].z;  acc1.w += wn * f[r][1].w;
    }
    part4[w * 64 + l]      = acc0;    // cols [4l, 4l+4)
    part4[w * 64 + 32 + l] = acc1;    // cols [128+4l, ...)
    __syncthreads();

    // Phase 3: cross-warp sum, thread tid owns column tid
    const float* partf = reinterpret_cast<const float*>(part4);
    float acc = 0.f;
    #pragma unroll
    for (int ww = 0; ww < 8; ww++)
        acc += partf[ww * D_SZ + tid];
    g_part[(b * NT + t) * D_SZ + tid] = acc;
}

// ---------------------------------------------------------------------------
// K2b fused: grid (4 e-quarters, 256 b).  combine stats -> gr[256] ->
// 64 e-columns of ctx (64x4 layout). q==0 column writes exact alpha.
// ---------------------------------------------------------------------------
__global__ void __launch_bounds__(256) k2b_fused(
    float* __restrict__ alpha_out,
    float* __restrict__ ctx)
{
    __shared__ float f_s[NT];
    __shared__ float sm_M, sm_invZ;
    __shared__ float gr[D_SZ];
    __shared__ float red[256];
    const int b = blockIdx.y;
    const int q = blockIdx.x;          // e-quarter
    const int e0 = q * 64;
    const int tid = threadIdx.x;

    if (tid < 32) {
        const float m_t = (tid < NT) ? g_mt[b * NT + tid] : -INFINITY;
        const float z_t = (tid < NT) ? g_zt[b * NT + tid] : 0.f;
        float M = m_t;
        #pragma unroll
        for (int off = 16; off > 0; off >>= 1)
            M = fmaxf(M, __shfl_xor_sync(0xffffffffu, M, off));
        const float e = (m_t == -INFINITY) ? 0.f : __expf(m_t - M);
        float Z = z_t * e;
        #pragma unroll
        for (int off = 16; off > 0; off >>= 1)
            Z += __shfl_xor_sync(0xffffffffu, Z, off);
        const float invZ = 1.f / Z;
        if (tid < NT) f_s[tid] = e * invZ;
        if (tid == 0) { sm_M = M; sm_invZ = invZ; }
    }
    __syncthreads();

    const float M = sm_M, invZ = sm_invZ;

    // exact alpha (only the q==0 CTA column writes it)
    if (q == 0) {
        alpha_out[b * N_SZ + tid] = __expf(g_s[b * N_SZ + tid] - M) * invZ;
        alpha_out[b * N_SZ + tid + 256] =
            __expf(g_s[b * N_SZ + tid + 256] - M) * invZ;
    }

    // g[b,d] = sum_t f_t * g_part[b,t,d]  -> smem (redundant per quarter)
    float acc = 0.f;
    #pragma unroll
    for (int t = 0; t < NT; t++)
        acc += f_s[t] * g_part[(b * NT + t) * D_SZ + tid];
    gr[tid] = acc;
    __syncthreads();

    // ctx[b, e0+c] partials: thread (c = tid&63, dg = tid>>6) sums 64 d's
    {
        const int c = tid & 63;
        const int dg = (tid >> 6) * 64;
        float c0 = 0.f, c1 = 0.f, c2 = 0.f, c3 = 0.f;
        #pragma unroll 4
        for (int dd = 0; dd < 64; dd += 4) {
            c0 += gr[dg + dd]     * g_WvT[(dg + dd)     * D_SZ + e0 + c];
            c1 += gr[dg + dd + 1] * g_WvT[(dg + dd + 1) * D_SZ + e0 + c];
            c2 += gr[dg + dd + 2] * g_WvT[(dg + dd + 2) * D_SZ + e0 + c];
            c3 += gr[dg + dd + 3] * g_WvT[(dg + dd + 3) * D_SZ + e0 + c];
        }
        red[tid] = (c0 + c1) + (c2 + c3);
    }
    __syncthreads();

    if (tid < 64)
        ctx[b * D_SZ + e0 + tid] =
            (red[tid] + red[tid + 64]) + (red[tid + 128] + red[tid + 192]);
}

// ---------------------------------------------------------------------------
extern "C" void kernel_launch(void* const* d_in, const int* in_sizes, int n_in,
                              void* d_out, int out_size) {
    const float* tok  = (const float*)d_in[0];
    const float* H    = (const float*)d_in[1];
    const int* mask   = (const int*)d_in[2];
    const float* Wq   = (const float*)d_in[3];
    const float* Wk   = (const float*)d_in[4];
    const float* Wv   = (const float*)d_in[5];
    const float* ls   = (const float*)d_in[6];

    float* out_alpha = (float*)d_out;                 // [256,512]
    float* out_ctx   = out_alpha + B_SZ * N_SZ;       // [256,256]

    k_prep<<<dim3(8, 8, 2), 256>>>(Wq, Wk, Wv);
    k1_p<<<dim3(8, 8), 256>>>(tok);
    k2a_pass<<<dim3(NT, B_SZ), 256>>>(H, mask, ls);
    k2b_fused<<<dim3(4, B_SZ), 256>>>(out_alpha, out_ctx);
}

// round 13
// speedup vs baseline: 3.3309x; 1.0290x over previous
#include <cuda_runtime.h>
#include <math.h>

#define B_SZ 256
#define N_SZ 512
#define D_SZ 256
#define R_SZ 64
#define NT   16         // n-tiles per batch
#define TN   32         // rows per n-tile

// Scratch (allocation-free: __device__ globals)
__device__ float g_M[D_SZ * D_SZ];          // M = Wq^T @ Wk
__device__ float g_WvT[D_SZ * D_SZ];        // WvT[d][e] = Wv[e][d]
__device__ float g_p[B_SZ * D_SZ];          // p = tok @ M
__device__ float g_s[B_SZ * N_SZ];          // masked+scaled scores
__device__ float g_mt[B_SZ * NT];           // tile max
__device__ float g_zt[B_SZ * NT];           // tile sum of exp
__device__ float g_part[B_SZ * NT * D_SZ];  // unnormalized partial g

// ---------------------------------------------------------------------------
// prep: z=0 -> M tile (M = Wq^T @ Wk);  z=1 -> Wv transpose tile
// ---------------------------------------------------------------------------
__global__ void __launch_bounds__(256) k_prep(
    const float* __restrict__ Wq,    // [64, 256]
    const float* __restrict__ Wk,    // [64, 256]
    const float* __restrict__ Wv)    // [256, 256]
{
    const int tid = threadIdx.x, tx = tid & 31, ty = tid >> 5;

    if (blockIdx.z == 0) {
        __shared__ float A[32][33];
        __shared__ float Bs[32][33];
        const int d0 = blockIdx.y * 32, j0 = blockIdx.x * 32;
        float acc[4] = {0.f, 0.f, 0.f, 0.f};

        for (int k0 = 0; k0 < R_SZ; k0 += 32) {
            #pragma unroll
            for (int r = 0; r < 4; r++) {
                const int kk = ty + 8 * r;
                A[kk][tx]  = Wq[(k0 + kk) * D_SZ + d0 + tx];
                Bs[kk][tx] = Wk[(k0 + kk) * D_SZ + j0 + tx];
            }
            __syncthreads();
            #pragma unroll
            for (int kk = 0; kk < 32; kk++) {
                const float bv = Bs[kk][tx];
                #pragma unroll
                for (int r = 0; r < 4; r++)
                    acc[r] += A[kk][ty + 8 * r] * bv;
            }
            __syncthreads();
        }
        #pragma unroll
        for (int r = 0; r < 4; r++)
            g_M[(d0 + ty + 8 * r) * D_SZ + j0 + tx] = acc[r];
    } else {
        __shared__ float T[32][33];
        const int e0 = blockIdx.x * 32, d0 = blockIdx.y * 32;
        #pragma unroll
        for (int r = 0; r < 4; r++)
            T[ty + 8 * r][tx] = Wv[(e0 + ty + 8 * r) * D_SZ + d0 + tx];
        __syncthreads();
        #pragma unroll
        for (int r = 0; r < 4; r++)
            g_WvT[(d0 + ty + 8 * r) * D_SZ + e0 + tx] = T[tx][ty + 8 * r];
    }
}

// ---------------------------------------------------------------------------
// k1: p[b,j] = sum_d tok[b,d] * M[d,j]
// ---------------------------------------------------------------------------
__global__ void __launch_bounds__(256) k1_p(const float* __restrict__ tok)
{
    __shared__ float As[32][33];
    __shared__ float Bs[32][33];
    const int j0 = blockIdx.x * 32, b0 = blockIdx.y * 32;
    const int tid = threadIdx.x, tx = tid & 31, ty = tid >> 5;
    float acc[4] = {0.f, 0.f, 0.f, 0.f};

    for (int d0 = 0; d0 < D_SZ; d0 += 32) {
        #pragma unroll
        for (int r = 0; r < 4; r++) {
            const int row = ty + 8 * r;
            As[row][tx] = tok[(b0 + row) * D_SZ + d0 + tx];
            Bs[row][tx] = g_M[(d0 + row) * D_SZ + j0 + tx];
        }
        __syncthreads();
        #pragma unroll
        for (int kk = 0; kk < 32; kk++) {
            const float bv = Bs[kk][tx];
            #pragma unroll
            for (int r = 0; r < 4; r++)
                acc[r] += As[ty + 8 * r][kk] * bv;
        }
        __syncthreads();
    }
    #pragma unroll
    for (int r = 0; r < 4; r++)
        g_p[(b0 + ty + 8 * r) * D_SZ + j0 + tx] = acc[r];
}

// ---------------------------------------------------------------------------
// K2a: ONE DRAM read of H; tile lives in registers (proven R11 version).
// ---------------------------------------------------------------------------
__global__ void __launch_bounds__(256) k2a_pass(
    const float* __restrict__ H,
    const int* __restrict__ mask,
    const float* __restrict__ log_scale)
{
    __shared__ __align__(16) float p_s[D_SZ];
    __shared__ float s_s[TN];
    __shared__ float w_s[TN];
    __shared__ __align__(16) float4 part4[8 * 64];   // 8 KB

    const int b = blockIdx.y;
    const int t = blockIdx.x;
    const int n0 = t * TN;
    const int tid = threadIdx.x;
    const int w = tid >> 5, l = tid & 31;

    p_s[tid] = g_p[b * D_SZ + tid];
    const float inv_scale = 1.f / fmaxf(__expf(log_scale[0]), 0.1f);
    __syncthreads();

    const float* Hb = H + (size_t)b * N_SZ * D_SZ + (size_t)n0 * D_SZ;
    const float4* p4 = reinterpret_cast<const float4*>(p_s);
    const float4 pf0 = p4[l];
    const float4 pf1 = p4[l + 32];

    // Phase 1: front-batch 8 LDG.128 (4 rows x 2 fragments), keep in regs
    float4 f[4][2];
    #pragma unroll
    for (int r = 0; r < 4; r++) {
        const float4* h4 = reinterpret_cast<const float4*>(Hb + (w + 8 * r) * D_SZ);
        f[r][0] = h4[l];
        f[r][1] = h4[l + 32];
    }

    float sc[4];
    #pragma unroll
    for (int r = 0; r < 4; r++) {
        sc[r] = f[r][0].x * pf0.x + f[r][0].y * pf0.y
              + f[r][0].z * pf0.z + f[r][0].w * pf0.w
              + f[r][1].x * pf1.x + f[r][1].y * pf1.y
              + f[r][1].z * pf1.z + f[r][1].w * pf1.w;
    }
    #pragma unroll
    for (int off = 16; off > 0; off >>= 1) {
        #pragma unroll
        for (int r = 0; r < 4; r++)
            sc[r] += __shfl_xor_sync(0xffffffffu, sc[r], off);
    }
    if (l == 0) {
        #pragma unroll
        for (int r = 0; r < 4; r++) {
            const int n = w + 8 * r;
            const float s = (mask[b * N_SZ + n0 + n] != 0)
                            ? sc[r] * inv_scale : -INFINITY;
            s_s[n] = s;
            g_s[b * N_SZ + n0 + n] = s;
        }
    }
    __syncthreads();

    // Tile-local stats (warp 0, one score per lane)
    if (w == 0) {
        const float v = s_s[l];
        float vm = v;
        #pragma unroll
        for (int off = 16; off > 0; off >>= 1)
            vm = fmaxf(vm, __shfl_xor_sync(0xffffffffu, vm, off));
        const float mu = (vm == -INFINITY) ? 0.f : vm;     // NaN guard
        const float wv = __expf(v - mu);                   // exp(-inf)=0
        w_s[l] = wv;
        float z = wv;
        #pragma unroll
        for (int off = 16; off > 0; off >>= 1)
            z += __shfl_xor_sync(0xffffffffu, z, off);
        if (l == 0) {
            g_mt[b * NT + t] = vm;
            g_zt[b * NT + t] = z;
        }
    }
    __syncthreads();

    // Phase 2: pure register accumulation into lane-owned columns
    float4 acc0 = make_float4(0.f, 0.f, 0.f, 0.f);
    float4 acc1 = make_float4(0.f, 0.f, 0.f, 0.f);
    #pragma unroll
    for (int r = 0; r < 4; r++) {
        const float wn = w_s[w + 8 * r];
        acc0.x += wn * f[r][0].x;  acc0.y += wn * f[r][0].y;
        acc0.z += wn * f[r][0].z;  acc0.w += wn * f[r][0].w;
        acc1.x += wn * f[r][1].x;  acc1.y += wn * f[r][1].y;
        acc1.z += wn * f[r][1].z;  acc1.w += wn * f[r][1].w;
    }
    part4[w * 64 + l]      = acc0;    // cols [4l, 4l+4)
    part4[w * 64 + 32 + l] = acc1;    // cols [128+4l, ...)
    __syncthreads();

    // Phase 3: cross-warp sum, thread tid owns column tid
    const float* partf = reinterpret_cast<const float*>(part4);
    float acc = 0.f;
    #pragma unroll
    for (int ww = 0; ww < 8; ww++)
        acc += partf[ww * D_SZ + tid];
    g_part[(b * NT + t) * D_SZ + tid] = acc;
}

// ---------------------------------------------------------------------------
// K2b fused v3: grid (4 e-quarters, 256 b).  combine stats -> gr[256] ->
// 64 e-columns of ctx via (16 e-quads x 16 d-groups) with LDG.128 on WvT.
// q==0 column writes exact alpha.
// ---------------------------------------------------------------------------
__global__ void __launch_bounds__(256) k2b_fused(
    float* __restrict__ alpha_out,
    float* __restrict__ ctx)
{
    __shared__ float f_s[NT];
    __shared__ float sm_M, sm_invZ;
    __shared__ float gr[D_SZ];
    __shared__ __align__(16) float red[16][68];   // [d-group][64 e + pad]
    const int b = blockIdx.y;
    const int q = blockIdx.x;          // e-quarter
    const int e0 = q * 64;
    const int tid = threadIdx.x;

    if (tid < 32) {
        const float m_t = (tid < NT) ? g_mt[b * NT + tid] : -INFINITY;
        const float z_t = (tid < NT) ? g_zt[b * NT + tid] : 0.f;
        float M = m_t;
        #pragma unroll
        for (int off = 16; off > 0; off >>= 1)
            M = fmaxf(M, __shfl_xor_sync(0xffffffffu, M, off));
        const float e = (m_t == -INFINITY) ? 0.f : __expf(m_t - M);
        float Z = z_t * e;
        #pragma unroll
        for (int off = 16; off > 0; off >>= 1)
            Z += __shfl_xor_sync(0xffffffffu, Z, off);
        const float invZ = 1.f / Z;
        if (tid < NT) f_s[tid] = e * invZ;
        if (tid == 0) { sm_M = M; sm_invZ = invZ; }
    }
    __syncthreads();

    const float M = sm_M, invZ = sm_invZ;

    // exact alpha (only the q==0 CTA column writes it)
    if (q == 0) {
        alpha_out[b * N_SZ + tid] = __expf(g_s[b * N_SZ + tid] - M) * invZ;
        alpha_out[b * N_SZ + tid + 256] =
            __expf(g_s[b * N_SZ + tid + 256] - M) * invZ;
    }

    // g[b,d] = sum_t f_t * g_part[b,t,d]  -> smem (redundant per quarter)
    float acc = 0.f;
    #pragma unroll
    for (int t = 0; t < NT; t++)
        acc += f_s[t] * g_part[(b * NT + t) * D_SZ + tid];
    gr[tid] = acc;
    __syncthreads();

    // ctx partials: thread (c4 = tid&15 -> 4 e-cols, dg = tid>>4 -> 16 d's)
    // 16 LDG.128 per thread on WvT, float4 accumulators.
    {
        const int c4 = tid & 15;            // e-quad index
        const int dg = tid >> 4;            // d-group (16 d's)
        const int d0 = dg * 16;
        const float4* wv4 = reinterpret_cast<const float4*>(
            g_WvT + (size_t)d0 * D_SZ + e0 + 4 * c4);
        float4 a = make_float4(0.f, 0.f, 0.f, 0.f);
        #pragma unroll
        for (int dd = 0; dd < 16; dd++) {
            const float4 wv = wv4[dd * (D_SZ / 4)];
            const float s = gr[d0 + dd];
            a.x += s * wv.x;  a.y += s * wv.y;
            a.z += s * wv.z;  a.w += s * wv.w;
        }
        *reinterpret_cast<float4*>(&red[dg][4 * c4]) = a;   // STS.128
    }
    __syncthreads();

    // final: thread tid<64 owns e-col tid; sum over 16 d-groups
    if (tid < 64) {
        float c = 0.f;
        #pragma unroll
        for (int dg = 0; dg < 16; dg++)
            c += red[dg][tid];
        ctx[b * D_SZ + e0 + tid] = c;
    }
}

// ---------------------------------------------------------------------------
extern "C" void kernel_launch(void* const* d_in, const int* in_sizes, int n_in,
                              void* d_out, int out_size) {
    const float* tok  = (const float*)d_in[0];
    const float* H    = (const float*)d_in[1];
    const int* mask   = (const int*)d_in[2];
    const float* Wq   = (const float*)d_in[3];
    const float* Wk   = (const float*)d_in[4];
    const float* Wv   = (const float*)d_in[5];
    const float* ls   = (const float*)d_in[6];

    float* out_alpha = (float*)d_out;                 // [256,512]
    float* out_ctx   = out_alpha + B_SZ * N_SZ;       // [256,256]

    k_prep<<<dim3(8, 8, 2), 256>>>(Wq, Wk, Wv);
    k1_p<<<dim3(8, 8), 256>>>(tok);
    k2a_pass<<<dim3(NT, B_SZ), 256>>>(H, mask, ls);
    k2b_fused<<<dim3(4, B_SZ), 256>>>(out_alpha, out_ctx);
}

// round 14
// speedup vs baseline: 3.4587x; 1.0384x over previous
#include <cuda_runtime.h>
#include <math.h>

#define B_SZ 256
#define N_SZ 512
#define D_SZ 256
#define R_SZ 64
#define NT   16         // n-tiles per batch
#define TN   32         // rows per n-tile

// Scratch (allocation-free: __device__ globals)
__device__ float g_M[D_SZ * D_SZ];          // M = Wq^T @ Wk
__device__ float g_WvT[D_SZ * D_SZ];        // WvT[d][e] = Wv[e][d]
__device__ float g_p[B_SZ * D_SZ];          // p = tok @ M
__device__ float g_s[B_SZ * N_SZ];          // masked+scaled scores
__device__ float g_mt[B_SZ * NT];           // tile max
__device__ float g_zt[B_SZ * NT];           // tile sum of exp
__device__ float g_part[B_SZ * NT * D_SZ];  // unnormalized partial g

// ---------------------------------------------------------------------------
// prep: z=0 -> M tile (M = Wq^T @ Wk);  z=1 -> Wv transpose tile
// ---------------------------------------------------------------------------
__global__ void __launch_bounds__(256) k_prep(
    const float* __restrict__ Wq,    // [64, 256]
    const float* __restrict__ Wk,    // [64, 256]
    const float* __restrict__ Wv)    // [256, 256]
{
    const int tid = threadIdx.x, tx = tid & 31, ty = tid >> 5;

    if (blockIdx.z == 0) {
        __shared__ float A[32][33];
        __shared__ float Bs[32][33];
        const int d0 = blockIdx.y * 32, j0 = blockIdx.x * 32;
        float acc[4] = {0.f, 0.f, 0.f, 0.f};

        for (int k0 = 0; k0 < R_SZ; k0 += 32) {
            #pragma unroll
            for (int r = 0; r < 4; r++) {
                const int kk = ty + 8 * r;
                A[kk][tx]  = Wq[(k0 + kk) * D_SZ + d0 + tx];
                Bs[kk][tx] = Wk[(k0 + kk) * D_SZ + j0 + tx];
            }
            __syncthreads();
            #pragma unroll
            for (int kk = 0; kk < 32; kk++) {
                const float bv = Bs[kk][tx];
                #pragma unroll
                for (int r = 0; r < 4; r++)
                    acc[r] += A[kk][ty + 8 * r] * bv;
            }
            __syncthreads();
        }
        #pragma unroll
        for (int r = 0; r < 4; r++)
            g_M[(d0 + ty + 8 * r) * D_SZ + j0 + tx] = acc[r];
    } else {
        __shared__ float T[32][33];
        const int e0 = blockIdx.x * 32, d0 = blockIdx.y * 32;
        #pragma unroll
        for (int r = 0; r < 4; r++)
            T[ty + 8 * r][tx] = Wv[(e0 + ty + 8 * r) * D_SZ + d0 + tx];
        __syncthreads();
        #pragma unroll
        for (int r = 0; r < 4; r++)
            g_WvT[(d0 + ty + 8 * r) * D_SZ + e0 + tx] = T[tx][ty + 8 * r];
    }
}

// ---------------------------------------------------------------------------
// k1: p[b,j] = sum_d tok[b,d] * M[d,j]
// ---------------------------------------------------------------------------
__global__ void __launch_bounds__(256) k1_p(const float* __restrict__ tok)
{
    __shared__ float As[32][33];
    __shared__ float Bs[32][33];
    const int j0 = blockIdx.x * 32, b0 = blockIdx.y * 32;
    const int tid = threadIdx.x, tx = tid & 31, ty = tid >> 5;
    float acc[4] = {0.f, 0.f, 0.f, 0.f};

    for (int d0 = 0; d0 < D_SZ; d0 += 32) {
        #pragma unroll
        for (int r = 0; r < 4; r++) {
            const int row = ty + 8 * r;
            As[row][tx] = tok[(b0 + row) * D_SZ + d0 + tx];
            Bs[row][tx] = g_M[(d0 + row) * D_SZ + j0 + tx];
        }
        __syncthreads();
        #pragma unroll
        for (int kk = 0; kk < 32; kk++) {
            const float bv = Bs[kk][tx];
            #pragma unroll
            for (int r = 0; r < 4; r++)
                acc[r] += As[ty + 8 * r][kk] * bv;
        }
        __syncthreads();
    }
    #pragma unroll
    for (int r = 0; r < 4; r++)
        g_p[(b0 + ty + 8 * r) * D_SZ + j0 + tx] = acc[r];
}

// ---------------------------------------------------------------------------
// K2a v2: ONE DRAM read of H, tile in registers.  Changes vs R12:
//  - H LDG.128s issued BEFORE the p_s load+barrier (hide p round-trip)
//  - per-warp uniform mask loads; masked scores broadcast in registers
//  - stats: all warps redundantly reduce max from s_s; weights computed in
//    registers -> one barrier and the w_s smem round-trip removed
// ---------------------------------------------------------------------------
__global__ void __launch_bounds__(256) k2a_pass(
    const float* __restrict__ H,
    const int* __restrict__ mask,
    const float* __restrict__ log_scale)
{
    __shared__ __align__(16) float p_s[D_SZ];
    __shared__ float s_s[TN];
    __shared__ __align__(16) float4 part4[8 * 64];   // 8 KB

    const int b = blockIdx.y;
    const int t = blockIdx.x;
    const int n0 = t * TN;
    const int tid = threadIdx.x;
    const int w = tid >> 5, l = tid & 31;

    const float* Hb = H + (size_t)b * N_SZ * D_SZ + (size_t)n0 * D_SZ;

    // 1) Front-batch the 8 H LDG.128 FIRST (no dependence on p)
    float4 f[4][2];
    #pragma unroll
    for (int r = 0; r < 4; r++) {
        const float4* h4 = reinterpret_cast<const float4*>(Hb + (w + 8 * r) * D_SZ);
        f[r][0] = h4[l];
        f[r][1] = h4[l + 32];
    }

    // 2) p load + mask (uniform per warp) + scale, overlapped with H latency
    p_s[tid] = g_p[b * D_SZ + tid];
    int mk[4];
    #pragma unroll
    for (int r = 0; r < 4; r++)
        mk[r] = mask[b * N_SZ + n0 + w + 8 * r];   // uniform addr per warp
    const float inv_scale = 1.f / fmaxf(__expf(log_scale[0]), 0.1f);
    __syncthreads();

    const float4* p4 = reinterpret_cast<const float4*>(p_s);
    const float4 pf0 = p4[l];
    const float4 pf1 = p4[l + 32];

    // 3) Dots + warp reduction; masked scores live in ALL lanes' registers
    float sc[4];
    #pragma unroll
    for (int r = 0; r < 4; r++) {
        sc[r] = f[r][0].x * pf0.x + f[r][0].y * pf0.y
              + f[r][0].z * pf0.z + f[r][0].w * pf0.w
              + f[r][1].x * pf1.x + f[r][1].y * pf1.y
              + f[r][1].z * pf1.z + f[r][1].w * pf1.w;
    }
    #pragma unroll
    for (int off = 16; off > 0; off >>= 1) {
        #pragma unroll
        for (int r = 0; r < 4; r++)
            sc[r] += __shfl_xor_sync(0xffffffffu, sc[r], off);
    }
    float s[4];
    #pragma unroll
    for (int r = 0; r < 4; r++)
        s[r] = mk[r] ? sc[r] * inv_scale : -INFINITY;

    if (l == 0) {
        #pragma unroll
        for (int r = 0; r < 4; r++) {
            s_s[w + 8 * r] = s[r];
            g_s[b * N_SZ + n0 + w + 8 * r] = s[r];
        }
    }
    __syncthreads();

    // 4) Stats: every warp redundantly computes tile max (1 LDS + shfl)
    {
        const float v = s_s[l];
        float vm = v;
        #pragma unroll
        for (int off = 16; off > 0; off >>= 1)
            vm = fmaxf(vm, __shfl_xor_sync(0xffffffffu, vm, off));
        const float mu = (vm == -INFINITY) ? 0.f : vm;     // NaN guard

        if (w == 0) {       // warp 0 also computes Z and stores stats
            float z = __expf(v - mu);                      // exp(-inf)=0
            #pragma unroll
            for (int off = 16; off > 0; off >>= 1)
                z += __shfl_xor_sync(0xffffffffu, z, off);
            if (l == 0) {
                g_mt[b * NT + t] = vm;
                g_zt[b * NT + t] = z;
            }
        }

        // weights for own rows, straight in registers
        #pragma unroll
        for (int r = 0; r < 4; r++)
            s[r] = __expf(s[r] - mu);
    }

    // 5) Phase 2: pure register accumulation (no barrier needed)
    float4 acc0 = make_float4(0.f, 0.f, 0.f, 0.f);
    float4 acc1 = make_float4(0.f, 0.f, 0.f, 0.f);
    #pragma unroll
    for (int r = 0; r < 4; r++) {
        const float wn = s[r];
        acc0.x += wn * f[r][0].x;  acc0.y += wn * f[r][0].y;
        acc0.z += wn * f[r][0].z;  acc0.w += wn * f[r][0].w;
        acc1.x += wn * f[r][1].x;  acc1.y += wn * f[r][1].y;
        acc1.z += wn * f[r][1].z;  acc1.w += wn * f[r][1].w;
    }
    part4[w * 64 + l]      = acc0;    // cols [4l, 4l+4)
    part4[w * 64 + 32 + l] = acc1;    // cols [128+4l, ...)
    __syncthreads();

    // 6) Cross-warp sum, thread tid owns column tid
    const float* partf = reinterpret_cast<const float*>(part4);
    float acc = 0.f;
    #pragma unroll
    for (int ww = 0; ww < 8; ww++)
        acc += partf[ww * D_SZ + tid];
    g_part[(b * NT + t) * D_SZ + tid] = acc;
}

// ---------------------------------------------------------------------------
// K2b fused v3 (R12-proven): grid (4 e-quarters, 256 b).
// ---------------------------------------------------------------------------
__global__ void __launch_bounds__(256) k2b_fused(
    float* __restrict__ alpha_out,
    float* __restrict__ ctx)
{
    __shared__ float f_s[NT];
    __shared__ float sm_M, sm_invZ;
    __shared__ float gr[D_SZ];
    __shared__ __align__(16) float red[16][68];   // [d-group][64 e + pad]
    const int b = blockIdx.y;
    const int q = blockIdx.x;          // e-quarter
    const int e0 = q * 64;
    const int tid = threadIdx.x;

    if (tid < 32) {
        const float m_t = (tid < NT) ? g_mt[b * NT + tid] : -INFINITY;
        const float z_t = (tid < NT) ? g_zt[b * NT + tid] : 0.f;
        float M = m_t;
        #pragma unroll
        for (int off = 16; off > 0; off >>= 1)
            M = fmaxf(M, __shfl_xor_sync(0xffffffffu, M, off));
        const float e = (m_t == -INFINITY) ? 0.f : __expf(m_t - M);
        float Z = z_t * e;
        #pragma unroll
        for (int off = 16; off > 0; off >>= 1)
            Z += __shfl_xor_sync(0xffffffffu, Z, off);
        const float invZ = 1.f / Z;
        if (tid < NT) f_s[tid] = e * invZ;
        if (tid == 0) { sm_M = M; sm_invZ = invZ; }
    }
    __syncthreads();

    const float M = sm_M, invZ = sm_invZ;

    // exact alpha (only the q==0 CTA column writes it)
    if (q == 0) {
        alpha_out[b * N_SZ + tid] = __expf(g_s[b * N_SZ + tid] - M) * invZ;
        alpha_out[b * N_SZ + tid + 256] =
            __expf(g_s[b * N_SZ + tid + 256] - M) * invZ;
    }

    // g[b,d] = sum_t f_t * g_part[b,t,d]  -> smem (redundant per quarter)
    float acc = 0.f;
    #pragma unroll
    for (int t = 0; t < NT; t++)
        acc += f_s[t] * g_part[(b * NT + t) * D_SZ + tid];
    gr[tid] = acc;
    __syncthreads();

    // ctx partials: thread (c4 = tid&15 -> 4 e-cols, dg = tid>>4 -> 16 d's)
    {
        const int c4 = tid & 15;            // e-quad index
        const int dg = tid >> 4;            // d-group (16 d's)
        const int d0 = dg * 16;
        const float4* wv4 = reinterpret_cast<const float4*>(
            g_WvT + (size_t)d0 * D_SZ + e0 + 4 * c4);
        float4 a = make_float4(0.f, 0.f, 0.f, 0.f);
        #pragma unroll
        for (int dd = 0; dd < 16; dd++) {
            const float4 wv = wv4[dd * (D_SZ / 4)];
            const float sv = gr[d0 + dd];
            a.x += sv * wv.x;  a.y += sv * wv.y;
            a.z += sv * wv.z;  a.w += sv * wv.w;
        }
        *reinterpret_cast<float4*>(&red[dg][4 * c4]) = a;   // STS.128
    }
    __syncthreads();

    if (tid < 64) {
        float c = 0.f;
        #pragma unroll
        for (int dg = 0; dg < 16; dg++)
            c += red[dg][tid];
        ctx[b * D_SZ + e0 + tid] = c;
    }
}

// ---------------------------------------------------------------------------
extern "C" void kernel_launch(void* const* d_in, const int* in_sizes, int n_in,
                              void* d_out, int out_size) {
    const float* tok  = (const float*)d_in[0];
    const float* H    = (const float*)d_in[1];
    const int* mask   = (const int*)d_in[2];
    const float* Wq   = (const float*)d_in[3];
    const float* Wk   = (const float*)d_in[4];
    const float* Wv   = (const float*)d_in[5];
    const float* ls   = (const float*)d_in[6];

    float* out_alpha = (float*)d_out;                 // [256,512]
    float* out_ctx   = out_alpha + B_SZ * N_SZ;       // [256,256]

    k_prep<<<dim3(8, 8, 2), 256>>>(Wq, Wk, Wv);
    k1_p<<<dim3(8, 8), 256>>>(tok);
    k2a_pass<<<dim3(NT, B_SZ), 256>>>(H, mask, ls);
    k2b_fused<<<dim3(4, B_SZ), 256>>>(out_alpha, out_ctx);
}